// round 1
// baseline (speedup 1.0000x reference)
#include <cuda_runtime.h>
#include <math.h>

// EstimateAdj: out = diag(1/rowsum(A*B + I)) @ (A*B + I), N=8192.
// One CTA per row; single read of A,B; single write of out.
// 256 threads x 32 elems/thread (8x float4) held in registers.

#define N 8192
#define N4 (N / 4)            // 2048 float4 per row
#define TPB 256
#define V_PER_T (N4 / TPB)    // 8 float4 per thread

__global__ __launch_bounds__(TPB, 4)
void estimate_adj_kernel(const float4* __restrict__ A,
                         const float4* __restrict__ B,
                         float4* __restrict__ out) {
    const int row = blockIdx.x;
    const long base = (long)row * N4;
    const int tid = threadIdx.x;

    float4 p[V_PER_T];
    float sum = 0.0f;

    // Load + multiply + diagonal injection. Front-batched loads (MLP).
    #pragma unroll
    for (int j = 0; j < V_PER_T; j++) {
        const int idx = tid + j * TPB;           // 0..2047, coalesced
        float4 a = A[base + idx];
        float4 b = B[base + idx];
        float4 m;
        m.x = a.x * b.x;
        m.y = a.y * b.y;
        m.z = a.z * b.z;
        m.w = a.w * b.w;
        if (idx == (row >> 2)) {
            // identity: element (row,row) -> float4 index row/4, lane row%4
            ((float*)&m)[row & 3] += 1.0f;
        }
        p[j] = m;
        sum += (m.x + m.y) + (m.z + m.w);
    }

    // Block reduction of rowsum: warp shuffle then smem across 8 warps.
    #pragma unroll
    for (int off = 16; off > 0; off >>= 1)
        sum += __shfl_xor_sync(0xFFFFFFFFu, sum, off);

    __shared__ float warp_sums[TPB / 32];
    __shared__ float rinv_s;
    const int lane = tid & 31;
    const int wid = tid >> 5;
    if (lane == 0) warp_sums[wid] = sum;
    __syncthreads();

    if (tid == 0) {
        float total = 0.0f;
        #pragma unroll
        for (int w = 0; w < TPB / 32; w++) total += warp_sums[w];
        float rinv = 1.0f / total;
        if (isinf(rinv)) rinv = 0.0f;
        rinv_s = rinv;
    }
    __syncthreads();

    const float rinv = rinv_s;

    // Scale and store from registers.
    #pragma unroll
    for (int j = 0; j < V_PER_T; j++) {
        const int idx = tid + j * TPB;
        float4 m = p[j];
        m.x *= rinv; m.y *= rinv; m.z *= rinv; m.w *= rinv;
        out[base + idx] = m;
    }
}

extern "C" void kernel_launch(void* const* d_in, const int* in_sizes, int n_in,
                              void* d_out, int out_size) {
    const float4* A = (const float4*)d_in[0];   // estimated_adj
    const float4* B = (const float4*)d_in[1];   // ori
    float4* out = (float4*)d_out;
    estimate_adj_kernel<<<N, TPB>>>(A, B, out);
}

// round 2
// speedup vs baseline: 1.0093x; 1.0093x over previous
#include <cuda_runtime.h>
#include <math.h>

// EstimateAdj: out = diag(1/rowsum(A*B + I)) @ (A*B + I), N=8192.
// One CTA per row; single read of A,B; single write of out.
// R2: 512 threads x 16 elems/thread (4x float4), single-barrier reduction,
//     reg-capped for 3 CTAs/SM -> higher occupancy to cover barrier bubble.

#define N 8192
#define N4 (N / 4)            // 2048 float4 per row
#define TPB 512
#define V_PER_T (N4 / TPB)    // 4 float4 per thread
#define NWARPS (TPB / 32)     // 16

__global__ __launch_bounds__(TPB, 3)
void estimate_adj_kernel(const float4* __restrict__ A,
                         const float4* __restrict__ B,
                         float4* __restrict__ out) {
    const int row = blockIdx.x;
    const long base = (long)row * N4;
    const int tid = threadIdx.x;
    const int diag4 = row >> 2;          // float4 index of the diagonal element

    float4 p[V_PER_T];
    float sum = 0.0f;

    // Load + multiply + diagonal injection. Coalesced, front-batched loads.
    #pragma unroll
    for (int j = 0; j < V_PER_T; j++) {
        const int idx = tid + j * TPB;   // 0..2047
        float4 a = A[base + idx];
        float4 b = B[base + idx];
        float4 m;
        m.x = a.x * b.x;
        m.y = a.y * b.y;
        m.z = a.z * b.z;
        m.w = a.w * b.w;
        if (idx == diag4) {
            ((float*)&m)[row & 3] += 1.0f;
        }
        p[j] = m;
        sum += (m.x + m.y) + (m.z + m.w);
    }

    // Warp reduction
    #pragma unroll
    for (int off = 16; off > 0; off >>= 1)
        sum += __shfl_xor_sync(0xFFFFFFFFu, sum, off);

    __shared__ float warp_sums[NWARPS];
    const int lane = tid & 31;
    const int wid = tid >> 5;
    if (lane == 0) warp_sums[wid] = sum;
    __syncthreads();

    // Every thread finishes the reduction itself (no second barrier).
    float total = 0.0f;
    #pragma unroll
    for (int w = 0; w < NWARPS; w++) total += warp_sums[w];
    float rinv = 1.0f / total;
    if (isinf(rinv)) rinv = 0.0f;

    // Scale and store from registers.
    #pragma unroll
    for (int j = 0; j < V_PER_T; j++) {
        const int idx = tid + j * TPB;
        float4 m = p[j];
        m.x *= rinv; m.y *= rinv; m.z *= rinv; m.w *= rinv;
        out[base + idx] = m;
    }
}

extern "C" void kernel_launch(void* const* d_in, const int* in_sizes, int n_in,
                              void* d_out, int out_size) {
    const float4* A = (const float4*)d_in[0];   // estimated_adj
    const float4* B = (const float4*)d_in[1];   // ori
    float4* out = (float4*)d_out;
    estimate_adj_kernel<<<N, TPB>>>(A, B, out);
}